// round 13
// baseline (speedup 1.0000x reference)
#include <cuda_runtime.h>
#include <cuda_fp16.h>
#include <cstdint>

// ---------------------------------------------------------------------------
// out[b,i,j] = sum_d relu(a[b,i,d] + c[b,j,d]) * W2[d] + b2
//   a = emb @ W1[:768] + b1,  c = emb @ W1[768:]
// emb (4,512,768) f32, W1 (1536,256), b1 (256), W2 (256,1), b2 (1)
// out (4,512,512) f32
//
//  prep : emb -> fp16 plane (batched loads); W1 -> B[n][k] fp16 plane
//  gemm : mma.sync m16n8k16 f16, 1 plane, CTA 128m x 64n, BK=64, 12 iters
//  pair : scalar relu-dot, 4-WAY split-d, 256 threads, 32x32 tile
// ---------------------------------------------------------------------------

#define B_   4
#define N_   512
#define H_   768
#define HID_ 256
#define M_   (B_ * N_)        // 2048

__device__ float g_a[HID_ * M_];                 // d-major: g_a[d*M_+m]
__device__ float g_c[HID_ * M_];
__device__ __half g_ef[M_ * H_];                 // emb fp16 [m][k]
__device__ __half g_bf[N_ * H_];                 // B[n][k] fp16, n = half*256+d

// ---------------- helpers ---------------------------------------------------
__device__ __forceinline__ uint32_t smem_u32(const void* p) {
    uint32_t a;
    asm("{ .reg .u64 t; cvta.to.shared.u64 t, %1; cvt.u32.u64 %0, t; }"
        : "=r"(a) : "l"(p));
    return a;
}
#define SW128(o) ((o) ^ (((o) >> 3) & 0x70))

__device__ __forceinline__ void cp_async16(uint32_t dst, const void* src) {
    asm volatile("cp.async.cg.shared.global [%0], [%1], 16;"
                 :: "r"(dst), "l"(src) : "memory");
}
__device__ __forceinline__ void cp_commit() {
    asm volatile("cp.async.commit_group;" ::: "memory");
}
__device__ __forceinline__ void cp_wait1() {
    asm volatile("cp.async.wait_group 1;" ::: "memory");
}
__device__ __forceinline__ void ldmx4(uint32_t addr, uint32_t* r) {
    asm volatile("ldmatrix.sync.aligned.m8n8.x4.shared.b16 {%0,%1,%2,%3}, [%4];"
                 : "=r"(r[0]), "=r"(r[1]), "=r"(r[2]), "=r"(r[3]) : "r"(addr));
}
__device__ __forceinline__ void mma16816(float* c, const uint32_t* a,
                                         uint32_t b0, uint32_t b1) {
    asm volatile(
        "mma.sync.aligned.m16n8k16.row.col.f32.f16.f16.f32 "
        "{%0,%1,%2,%3}, {%4,%5,%6,%7}, {%8,%9}, {%0,%1,%2,%3};"
        : "+f"(c[0]), "+f"(c[1]), "+f"(c[2]), "+f"(c[3])
        : "r"(a[0]), "r"(a[1]), "r"(a[2]), "r"(a[3]), "r"(b0), "r"(b1));
}
// packed fp32x2
__device__ __forceinline__ float2 ffma2(float2 a, float2 b, float2 c) {
    union F2U { float2 f; unsigned long long u; };
    F2U A, Bv, C, D;
    A.f = a; Bv.f = b; C.f = c;
    asm("fma.rn.f32x2 %0, %1, %2, %3;" : "=l"(D.u) : "l"(A.u), "l"(Bv.u), "l"(C.u));
    return D.f;
}
__device__ __forceinline__ float2 fadd2(float2 a, float2 b) {
    union F2U { float2 f; unsigned long long u; };
    F2U A, Bv, D;
    A.f = a; Bv.f = b;
    asm("add.rn.f32x2 %0, %1, %2;" : "=l"(D.u) : "l"(A.u), "l"(Bv.u));
    return D.f;
}

// ---------------------------------------------------------------------------
// FUSED prep: blocks [0,384) convert emb -> fp16 (4 strided float4 / thread);
//             blocks [384,480) transpose+convert W1 -> fp16.
// ---------------------------------------------------------------------------
#define EMB_BLOCKS 384
#define W_BLOCKS   96
#define EMB_STRIDE (EMB_BLOCKS * 256 * 4)   // elems per pass

__global__ void __launch_bounds__(256)
prep_kernel(const float* __restrict__ emb, const float* __restrict__ W1)
{
    const int t = threadIdx.x;

    if (blockIdx.x < EMB_BLOCKS) {
        const int idx = (blockIdx.x * 256 + t) * 4;
        float4 v[4];
        #pragma unroll
        for (int u = 0; u < 4; u++)
            v[u] = *(const float4*)&emb[idx + u * EMB_STRIDE];
        #pragma unroll
        for (int u = 0; u < 4; u++) {
            __half2 p0(__float2half(v[u].x), __float2half(v[u].y));
            __half2 p1(__float2half(v[u].z), __float2half(v[u].w));
            *(__half2*)&g_ef[idx + u * EMB_STRIDE]     = p0;
            *(__half2*)&g_ef[idx + u * EMB_STRIDE + 2] = p1;
        }
        return;
    }

    __shared__ float tile[128][33];
    const int bid  = blockIdx.x - EMB_BLOCKS;
    const int d0   = (bid & 7) * 32;
    const int k0   = ((bid >> 3) % 6) * 128;
    const int half = bid / 48;

    {
        const int kk = t >> 3, dd = (t & 7) * 4;
        #pragma unroll
        for (int p = 0; p < 4; p++) {
            float4 v = *(const float4*)&W1[(half * H_ + k0 + kk + p * 32) * HID_ + d0 + dd];
            tile[kk + p * 32][dd]     = v.x;
            tile[kk + p * 32][dd + 1] = v.y;
            tile[kk + p * 32][dd + 2] = v.z;
            tile[kk + p * 32][dd + 3] = v.w;
        }
    }
    __syncthreads();

    #pragma unroll
    for (int e = 0; e < 2; e++) {
        const int cid = t * 2 + e;
        const int nl  = cid >> 4;
        const int kc  = (cid & 15) * 8;
        uint32_t hv[4];
        #pragma unroll
        for (int u = 0; u < 4; u++) {
            __half2 hp(__float2half(tile[kc + 2*u][nl]),
                       __float2half(tile[kc + 2*u + 1][nl]));
            hv[u] = *(uint32_t*)&hp;
        }
        const int n = half * HID_ + d0 + nl;
        const int o = n * H_ + k0 + kc;
        *(uint4*)&g_bf[o] = make_uint4(hv[0], hv[1], hv[2], hv[3]);
    }
}

// ---------------------------------------------------------------------------
// GEMM (unchanged, ~6.5us): single fp16 plane, CTA 128m x 64n, BK=64,
// 12 iters, cp.async distance-2, SW128. Grid 8 x 16 = 128 CTAs.
// ---------------------------------------------------------------------------
#define GITER 12
#define A_BUF_BYTES (128 * 128)
#define B_BUF_BYTES (64 * 128)

__global__ void __launch_bounds__(256)
gemm_kernel(const float* __restrict__ b1)
{
    __shared__ __align__(1024) unsigned char sraw[2 * A_BUF_BYTES + 2 * B_BUF_BYTES];

    const int t      = threadIdx.x;
    const int lane   = t & 31;
    const int wid    = t >> 5;
    const int warp_m = wid & 3;
    const int warp_n = wid >> 2;
    const int m0     = blockIdx.y * 128;
    const int ng0    = blockIdx.x * 64;
    const int half   = ng0 >> 8;
    const int d0     = ng0 & 255;

    const uint32_t smemA = smem_u32(sraw);
    const uint32_t smemB = smemA + 2 * A_BUF_BYTES;

    auto fill = [&](int buf, int it) {
        const int k0 = it * 64;
        const uint32_t ab = smemA + buf * A_BUF_BYTES;
        const uint32_t bb = smemB + buf * B_BUF_BYTES;
        #pragma unroll
        for (int e = 0; e < 4; e++) {
            const int slot = t + e * 256;
            const int row = slot >> 3, seg = slot & 7;
            const uint32_t off = (uint32_t)(row * 128 + seg * 16);
            cp_async16(ab + SW128(off), &g_ef[(m0 + row) * H_ + k0 + seg * 8]);
        }
        #pragma unroll
        for (int e = 0; e < 2; e++) {
            const int slot = t + e * 256;
            const int row = slot >> 3, seg = slot & 7;
            const uint32_t off = (uint32_t)(row * 128 + seg * 16);
            cp_async16(bb + SW128(off), &g_bf[(ng0 + row) * H_ + k0 + seg * 8]);
        }
    };

    const uint32_t csel  = (uint32_t)((lane >> 4) * 16);
    const uint32_t maskx = (uint32_t)((lane & 7) * 16);
    const uint32_t aoff0 = (uint32_t)((warp_m * 32 + (lane & 15)) * 128);
    const uint32_t aoff1 = aoff0 + 16 * 128;
    const uint32_t boff0 = (uint32_t)((warp_n * 32 + (lane & 15)) * 128);
    const uint32_t boff1 = boff0 + 16 * 128;

    float acc[2][4][4];
    #pragma unroll
    for (int mf = 0; mf < 2; mf++)
        #pragma unroll
        for (int nf = 0; nf < 4; nf++)
            #pragma unroll
            for (int e = 0; e < 4; e++) acc[mf][nf][e] = 0.f;

    fill(0, 0); cp_commit();
    fill(1, 1); cp_commit();

    for (int it = 0; it < GITER; it++) {
        const int cur = it & 1;
        cp_wait1();
        __syncthreads();

        const uint32_t ab = smemA + cur * A_BUF_BYTES;
        const uint32_t bb = smemB + cur * B_BUF_BYTES;
        #pragma unroll
        for (int kk = 0; kk < 4; kk++) {
            const uint32_t col = ((uint32_t)(kk * 32) + csel) ^ maskx;
            uint32_t a0[4], a1[4], b0[4], b1r[4];
            ldmx4(ab + aoff0 + col, a0);
            ldmx4(ab + aoff1 + col, a1);
            ldmx4(bb + boff0 + col, b0);
            ldmx4(bb + boff1 + col, b1r);
            mma16816(acc[0][0], a0, b0[0],  b0[2]);
            mma16816(acc[0][1], a0, b0[1],  b0[3]);
            mma16816(acc[0][2], a0, b1r[0], b1r[2]);
            mma16816(acc[0][3], a0, b1r[1], b1r[3]);
            mma16816(acc[1][0], a1, b0[0],  b0[2]);
            mma16816(acc[1][1], a1, b0[1],  b0[3]);
            mma16816(acc[1][2], a1, b1r[0], b1r[2]);
            mma16816(acc[1][3], a1, b1r[1], b1r[3]);
        }

        if (it + 2 < GITER) {
            __syncthreads();
            fill(cur, it + 2);
        }
        cp_commit();
    }

    float* __restrict__ gout = half ? g_c : g_a;
    const int mrow = m0 + warp_m * 32 + (lane >> 2);
    #pragma unroll
    for (int mf = 0; mf < 2; mf++) {
        const int m = mrow + mf * 16;
        #pragma unroll
        for (int nf = 0; nf < 4; nf++) {
            const int nl = warp_n * 32 + nf * 8 + (lane & 3) * 2;
            float bias0 = 0.f, bias1 = 0.f;
            if (half == 0) { bias0 = b1[d0 + nl]; bias1 = b1[d0 + nl + 1]; }
            const int d = d0 + nl;
            gout[d       * M_ + m]     = acc[mf][nf][0] + bias0;
            gout[(d + 1) * M_ + m]     = acc[mf][nf][1] + bias1;
            gout[d       * M_ + m + 8] = acc[mf][nf][2] + bias0;
            gout[(d + 1) * M_ + m + 8] = acc[mf][nf][3] + bias1;
        }
    }
}

// ---------------------------------------------------------------------------
// Pair kernel: 4-WAY SPLIT-D. 32x32 output tile, 256 threads (8 warps).
// Group g = t>>6 handles d in [g*64, (g+1)*64); each group's 64 threads cover
// the full 32x32 tile (4i x 4j per thread). smem reduction combines 4 partials.
// cp.async distance-2. Grid 16x16x4 = 1024 blocks; ~40+ warps/SM resident.
// ---------------------------------------------------------------------------
#define PDK    8
#define PITERS 8          // 64 d per group / PDK
#define PA_BUF (4 * PDK * 32 * 4)   // 4 groups x 8 dk x 32 m x 4B = 4KB

__global__ void __launch_bounds__(256, 5)
pair_kernel(const float* __restrict__ W2, const float* __restrict__ b2,
            float* __restrict__ out)
{
    __shared__ __align__(16) float As[2][4][PDK][32];   // 8KB
    __shared__ __align__(16) float Cs[2][4][PDK][32];   // 8KB
    __shared__ float Ws2[2 * HID_];                     // 2KB (duplicated pairs)
    __shared__ float red[3][64][20];                    // 15KB

    const int b  = blockIdx.z;
    const int i0 = blockIdx.y * 32;
    const int j0 = blockIdx.x * 32;
    const int ma = b * N_ + i0;
    const int mc = b * N_ + j0;

    const int t  = threadIdx.x;        // 256
    const int hd = t >> 6;             // d-group 0..3
    const int tl = t & 63;
    const int tx = t & 7;              // 4 j each
    const int ty = (t >> 3) & 7;       // 4 i each

    {
        const float w = W2[t];
        *(float2*)&Ws2[2 * t] = make_float2(w, w);
    }

    const uint32_t sA = smem_u32(As);
    const uint32_t sC = smem_u32(Cs);

    // fill: thread t -> chunk t: group = t>>6, dk = (t>>3)&7, seg = t&7.
    // smem offset c*16 matches As[buf][group][dk][seg*4] exactly.
    auto fill = [&](int buf, int it) {
        const int h  = t >> 6;
        const int dk = (t >> 3) & 7;
        const int sg = t & 7;
        const int d  = h * 64 + it * PDK + dk;
        const uint32_t dst = (uint32_t)(buf * PA_BUF + t * 16);
        cp_async16(sA + dst, &g_a[d * M_ + ma + sg * 4]);
        cp_async16(sC + dst, &g_c[d * M_ + mc + sg * 4]);
    };

    fill(0, 0); cp_commit();
    fill(1, 1); cp_commit();

    float2 acc[4][2];
    #pragma unroll
    for (int mi = 0; mi < 4; mi++) {
        acc[mi][0] = make_float2(0.f, 0.f);
        acc[mi][1] = make_float2(0.f, 0.f);
    }

    for (int it = 0; it < PITERS; it++) {
        const int cur = it & 1;
        cp_wait1();
        __syncthreads();

        const int dbase = hd * 64 + it * PDK;
        #pragma unroll
        for (int g = 0; g < PDK / 4; g++) {
            const float4 wva = *(const float4*)&Ws2[2 * (dbase + g * 4)];
            const float4 wvb = *(const float4*)&Ws2[2 * (dbase + g * 4) + 4];
            const float2 wp[4] = {
                make_float2(wva.x, wva.y), make_float2(wva.z, wva.w),
                make_float2(wvb.x, wvb.y), make_float2(wvb.z, wvb.w)
            };
            #pragma unroll
            for (int e = 0; e < 4; e++) {
                const int dk = g * 4 + e;
                const float4 av = *(const float4*)&As[cur][hd][dk][ty * 4];
                const float4 cv = *(const float4*)&Cs[cur][hd][dk][tx * 4];
                const float2 c01 = make_float2(cv.x, cv.y);
                const float2 c23 = make_float2(cv.z, cv.w);
                const float am[4] = {av.x, av.y, av.z, av.w};
                #pragma unroll
                for (int mi = 0; mi < 4; mi++) {
                    const float2 ap = make_float2(am[mi], am[mi]);
                    float2 s0 = fadd2(ap, c01);
                    float2 s1 = fadd2(ap, c23);
                    s0.x = fmaxf(s0.x, 0.f); s0.y = fmaxf(s0.y, 0.f);
                    s1.x = fmaxf(s1.x, 0.f); s1.y = fmaxf(s1.y, 0.f);
                    acc[mi][0] = ffma2(s0, wp[e], acc[mi][0]);
                    acc[mi][1] = ffma2(s1, wp[e], acc[mi][1]);
                }
            }
        }

        if (it + 2 < PITERS) {
            __syncthreads();
            fill(cur, it + 2);
        }
        cp_commit();
    }

    // reduction: groups 1..3 write partials, group 0 combines + stores
    if (hd != 0) {
        #pragma unroll
        for (int mi = 0; mi < 4; mi++)
            *(float4*)&red[hd - 1][tl][mi * 4] =
                make_float4(acc[mi][0].x, acc[mi][0].y,
                            acc[mi][1].x, acc[mi][1].y);
    }
    __syncthreads();
    if (hd == 0) {
        const float bb = b2[0];
        const int j = j0 + tx * 4;
        #pragma unroll
        for (int mi = 0; mi < 4; mi++) {
            float4 s = make_float4(acc[mi][0].x, acc[mi][0].y,
                                   acc[mi][1].x, acc[mi][1].y);
            #pragma unroll
            for (int r = 0; r < 3; r++) {
                const float4 p = *(const float4*)&red[r][tl][mi * 4];
                s.x += p.x; s.y += p.y; s.z += p.z; s.w += p.w;
            }
            const int i = i0 + ty * 4 + mi;
            float4 o;
            o.x = s.x + bb; o.y = s.y + bb; o.z = s.z + bb; o.w = s.w + bb;
            *(float4*)&out[((size_t)b * N_ + i) * N_ + j] = o;
        }
    }
}

// ---------------------------------------------------------------------------
extern "C" void kernel_launch(void* const* d_in, const int* in_sizes, int n_in,
                              void* d_out, int out_size)
{
    const float* emb = (const float*)d_in[0];
    const float* W1  = (const float*)d_in[1];
    const float* b1  = (const float*)d_in[2];
    const float* W2  = (const float*)d_in[3];
    const float* b2  = (const float*)d_in[4];
    float* out = (float*)d_out;

    prep_kernel<<<EMB_BLOCKS + W_BLOCKS, 256>>>(emb, W1);    // 480 blocks

    dim3 ggrid(N_ / 64, M_ / 128);                           // 8 x 16 = 128
    gemm_kernel<<<ggrid, 256>>>(b1);

    dim3 pgrid(N_ / 32, N_ / 32, B_);                        // 16 x 16 x 4
    pair_kernel<<<pgrid, 256>>>(W2, b2, out);
}

// round 14
// speedup vs baseline: 1.0460x; 1.0460x over previous
#include <cuda_runtime.h>
#include <cuda_fp16.h>
#include <cstdint>

// ---------------------------------------------------------------------------
// out[b,i,j] = sum_d relu(a[b,i,d] + c[b,j,d]) * W2[d] + b2
//   a = emb @ W1[:768] + b1,  c = emb @ W1[768:]
// emb (4,512,768) f32, W1 (1536,256), b1 (256), W2 (256,1), b2 (1)
// out (4,512,512) f32
//
//  prep : emb -> fp16 plane (batched); W1 -> B[n][k] fp16 plane  (R13, 6.3us)
//  gemm : mma.sync f16, 1 plane, CTA 128m x 64n, BK=64          (R12, ~6.5us)
//  pair : scalar relu-dot, 2-way split-d, PDK=32 (4 syncs instead of 8)
// ---------------------------------------------------------------------------

#define B_   4
#define N_   512
#define H_   768
#define HID_ 256
#define M_   (B_ * N_)        // 2048

__device__ float g_a[HID_ * M_];                 // d-major: g_a[d*M_+m]
__device__ float g_c[HID_ * M_];
__device__ __half g_ef[M_ * H_];                 // emb fp16 [m][k]
__device__ __half g_bf[N_ * H_];                 // B[n][k] fp16, n = half*256+d

// ---------------- helpers ---------------------------------------------------
__device__ __forceinline__ uint32_t smem_u32(const void* p) {
    uint32_t a;
    asm("{ .reg .u64 t; cvta.to.shared.u64 t, %1; cvt.u32.u64 %0, t; }"
        : "=r"(a) : "l"(p));
    return a;
}
#define SW128(o) ((o) ^ (((o) >> 3) & 0x70))

__device__ __forceinline__ void cp_async16(uint32_t dst, const void* src) {
    asm volatile("cp.async.cg.shared.global [%0], [%1], 16;"
                 :: "r"(dst), "l"(src) : "memory");
}
__device__ __forceinline__ void cp_commit() {
    asm volatile("cp.async.commit_group;" ::: "memory");
}
__device__ __forceinline__ void cp_wait1() {
    asm volatile("cp.async.wait_group 1;" ::: "memory");
}
__device__ __forceinline__ void ldmx4(uint32_t addr, uint32_t* r) {
    asm volatile("ldmatrix.sync.aligned.m8n8.x4.shared.b16 {%0,%1,%2,%3}, [%4];"
                 : "=r"(r[0]), "=r"(r[1]), "=r"(r[2]), "=r"(r[3]) : "r"(addr));
}
__device__ __forceinline__ void mma16816(float* c, const uint32_t* a,
                                         uint32_t b0, uint32_t b1) {
    asm volatile(
        "mma.sync.aligned.m16n8k16.row.col.f32.f16.f16.f32 "
        "{%0,%1,%2,%3}, {%4,%5,%6,%7}, {%8,%9}, {%0,%1,%2,%3};"
        : "+f"(c[0]), "+f"(c[1]), "+f"(c[2]), "+f"(c[3])
        : "r"(a[0]), "r"(a[1]), "r"(a[2]), "r"(a[3]), "r"(b0), "r"(b1));
}
// packed fp32x2
__device__ __forceinline__ float2 ffma2(float2 a, float2 b, float2 c) {
    union F2U { float2 f; unsigned long long u; };
    F2U A, Bv, C, D;
    A.f = a; Bv.f = b; C.f = c;
    asm("fma.rn.f32x2 %0, %1, %2, %3;" : "=l"(D.u) : "l"(A.u), "l"(Bv.u), "l"(C.u));
    return D.f;
}
__device__ __forceinline__ float2 fadd2(float2 a, float2 b) {
    union F2U { float2 f; unsigned long long u; };
    F2U A, Bv, D;
    A.f = a; Bv.f = b;
    asm("add.rn.f32x2 %0, %1, %2;" : "=l"(D.u) : "l"(A.u), "l"(Bv.u));
    return D.f;
}

// ---------------------------------------------------------------------------
// FUSED prep (R13): blocks [0,384) emb -> fp16 (4 strided float4 / thread);
//                   blocks [384,480) transpose+convert W1 -> fp16.
// ---------------------------------------------------------------------------
#define EMB_BLOCKS 384
#define W_BLOCKS   96
#define EMB_STRIDE (EMB_BLOCKS * 256 * 4)

__global__ void __launch_bounds__(256)
prep_kernel(const float* __restrict__ emb, const float* __restrict__ W1)
{
    const int t = threadIdx.x;

    if (blockIdx.x < EMB_BLOCKS) {
        const int idx = (blockIdx.x * 256 + t) * 4;
        float4 v[4];
        #pragma unroll
        for (int u = 0; u < 4; u++)
            v[u] = *(const float4*)&emb[idx + u * EMB_STRIDE];
        #pragma unroll
        for (int u = 0; u < 4; u++) {
            __half2 p0(__float2half(v[u].x), __float2half(v[u].y));
            __half2 p1(__float2half(v[u].z), __float2half(v[u].w));
            *(__half2*)&g_ef[idx + u * EMB_STRIDE]     = p0;
            *(__half2*)&g_ef[idx + u * EMB_STRIDE + 2] = p1;
        }
        return;
    }

    __shared__ float tile[128][33];
    const int bid  = blockIdx.x - EMB_BLOCKS;
    const int d0   = (bid & 7) * 32;
    const int k0   = ((bid >> 3) % 6) * 128;
    const int half = bid / 48;

    {
        const int kk = t >> 3, dd = (t & 7) * 4;
        #pragma unroll
        for (int p = 0; p < 4; p++) {
            float4 v = *(const float4*)&W1[(half * H_ + k0 + kk + p * 32) * HID_ + d0 + dd];
            tile[kk + p * 32][dd]     = v.x;
            tile[kk + p * 32][dd + 1] = v.y;
            tile[kk + p * 32][dd + 2] = v.z;
            tile[kk + p * 32][dd + 3] = v.w;
        }
    }
    __syncthreads();

    #pragma unroll
    for (int e = 0; e < 2; e++) {
        const int cid = t * 2 + e;
        const int nl  = cid >> 4;
        const int kc  = (cid & 15) * 8;
        uint32_t hv[4];
        #pragma unroll
        for (int u = 0; u < 4; u++) {
            __half2 hp(__float2half(tile[kc + 2*u][nl]),
                       __float2half(tile[kc + 2*u + 1][nl]));
            hv[u] = *(uint32_t*)&hp;
        }
        const int n = half * HID_ + d0 + nl;
        const int o = n * H_ + k0 + kc;
        *(uint4*)&g_bf[o] = make_uint4(hv[0], hv[1], hv[2], hv[3]);
    }
}

// ---------------------------------------------------------------------------
// GEMM (R12, unchanged): single fp16 plane, CTA 128m x 64n, BK=64, 12 iters,
// cp.async distance-2, SW128. Grid 8 x 16 = 128 CTAs.
// ---------------------------------------------------------------------------
#define GITER 12
#define A_BUF_BYTES (128 * 128)
#define B_BUF_BYTES (64 * 128)

__global__ void __launch_bounds__(256)
gemm_kernel(const float* __restrict__ b1)
{
    __shared__ __align__(1024) unsigned char sraw[2 * A_BUF_BYTES + 2 * B_BUF_BYTES];

    const int t      = threadIdx.x;
    const int lane   = t & 31;
    const int wid    = t >> 5;
    const int warp_m = wid & 3;
    const int warp_n = wid >> 2;
    const int m0     = blockIdx.y * 128;
    const int ng0    = blockIdx.x * 64;
    const int half   = ng0 >> 8;
    const int d0     = ng0 & 255;

    const uint32_t smemA = smem_u32(sraw);
    const uint32_t smemB = smemA + 2 * A_BUF_BYTES;

    auto fill = [&](int buf, int it) {
        const int k0 = it * 64;
        const uint32_t ab = smemA + buf * A_BUF_BYTES;
        const uint32_t bb = smemB + buf * B_BUF_BYTES;
        #pragma unroll
        for (int e = 0; e < 4; e++) {
            const int slot = t + e * 256;
            const int row = slot >> 3, seg = slot & 7;
            const uint32_t off = (uint32_t)(row * 128 + seg * 16);
            cp_async16(ab + SW128(off), &g_ef[(m0 + row) * H_ + k0 + seg * 8]);
        }
        #pragma unroll
        for (int e = 0; e < 2; e++) {
            const int slot = t + e * 256;
            const int row = slot >> 3, seg = slot & 7;
            const uint32_t off = (uint32_t)(row * 128 + seg * 16);
            cp_async16(bb + SW128(off), &g_bf[(ng0 + row) * H_ + k0 + seg * 8]);
        }
    };

    const uint32_t csel  = (uint32_t)((lane >> 4) * 16);
    const uint32_t maskx = (uint32_t)((lane & 7) * 16);
    const uint32_t aoff0 = (uint32_t)((warp_m * 32 + (lane & 15)) * 128);
    const uint32_t aoff1 = aoff0 + 16 * 128;
    const uint32_t boff0 = (uint32_t)((warp_n * 32 + (lane & 15)) * 128);
    const uint32_t boff1 = boff0 + 16 * 128;

    float acc[2][4][4];
    #pragma unroll
    for (int mf = 0; mf < 2; mf++)
        #pragma unroll
        for (int nf = 0; nf < 4; nf++)
            #pragma unroll
            for (int e = 0; e < 4; e++) acc[mf][nf][e] = 0.f;

    fill(0, 0); cp_commit();
    fill(1, 1); cp_commit();

    for (int it = 0; it < GITER; it++) {
        const int cur = it & 1;
        cp_wait1();
        __syncthreads();

        const uint32_t ab = smemA + cur * A_BUF_BYTES;
        const uint32_t bb = smemB + cur * B_BUF_BYTES;
        #pragma unroll
        for (int kk = 0; kk < 4; kk++) {
            const uint32_t col = ((uint32_t)(kk * 32) + csel) ^ maskx;
            uint32_t a0[4], a1[4], b0[4], b1r[4];
            ldmx4(ab + aoff0 + col, a0);
            ldmx4(ab + aoff1 + col, a1);
            ldmx4(bb + boff0 + col, b0);
            ldmx4(bb + boff1 + col, b1r);
            mma16816(acc[0][0], a0, b0[0],  b0[2]);
            mma16816(acc[0][1], a0, b0[1],  b0[3]);
            mma16816(acc[0][2], a0, b1r[0], b1r[2]);
            mma16816(acc[0][3], a0, b1r[1], b1r[3]);
            mma16816(acc[1][0], a1, b0[0],  b0[2]);
            mma16816(acc[1][1], a1, b0[1],  b0[3]);
            mma16816(acc[1][2], a1, b1r[0], b1r[2]);
            mma16816(acc[1][3], a1, b1r[1], b1r[3]);
        }

        if (it + 2 < GITER) {
            __syncthreads();
            fill(cur, it + 2);
        }
        cp_commit();
    }

    float* __restrict__ gout = half ? g_c : g_a;
    const int mrow = m0 + warp_m * 32 + (lane >> 2);
    #pragma unroll
    for (int mf = 0; mf < 2; mf++) {
        const int m = mrow + mf * 16;
        #pragma unroll
        for (int nf = 0; nf < 4; nf++) {
            const int nl = warp_n * 32 + nf * 8 + (lane & 3) * 2;
            float bias0 = 0.f, bias1 = 0.f;
            if (half == 0) { bias0 = b1[d0 + nl]; bias1 = b1[d0 + nl + 1]; }
            const int d = d0 + nl;
            gout[d       * M_ + m]     = acc[mf][nf][0] + bias0;
            gout[(d + 1) * M_ + m]     = acc[mf][nf][1] + bias1;
            gout[d       * M_ + m + 8] = acc[mf][nf][2] + bias0;
            gout[(d + 1) * M_ + m + 8] = acc[mf][nf][3] + bias1;
        }
    }
}

// ---------------------------------------------------------------------------
// Pair kernel: 2-way SPLIT-D (R8 topology), PDK=32 -> only 4 sync iterations.
// 32x32 tile, 128 threads; warps 0-1: d in [0,128), warps 2-3: d in [128,256).
// cp.async distance-2; smem reduction epilogue.
// ---------------------------------------------------------------------------
#define PDK    32
#define PITERS 4          // 128 d per group / PDK
#define PA_BUF (2 * PDK * 32 * 4)   // per buffer: 2 groups x 32dk x 32m x 4B = 8KB

__global__ void __launch_bounds__(128, 5)
pair_kernel(const float* __restrict__ W2, const float* __restrict__ b2,
            float* __restrict__ out)
{
    __shared__ __align__(16) float As[2][2][PDK][32];   // 16KB
    __shared__ __align__(16) float Cs[2][2][PDK][32];   // 16KB
    __shared__ float Ws2[2 * HID_];                     // 2KB duplicated pairs
    __shared__ float red[64][20];                       // 5KB

    const int b  = blockIdx.z;
    const int i0 = blockIdx.y * 32;
    const int j0 = blockIdx.x * 32;
    const int ma = b * N_ + i0;
    const int mc = b * N_ + j0;

    const int t  = threadIdx.x;        // 128
    const int hd = t >> 6;             // d-half 0/1
    const int tx = t & 7;              // 4 j each
    const int ty = (t >> 3) & 7;       // 4 i each

    #pragma unroll
    for (int u = 0; u < 2; u++) {
        const float w = W2[t + 128 * u];
        *(float2*)&Ws2[2 * (t + 128 * u)] = make_float2(w, w);
    }

    const uint32_t sA = smem_u32(As);
    const uint32_t sC = smem_u32(Cs);

    // fill: 512 16B-chunks per array per buffer -> 4 chunks/thread each.
    // chunk c: h = c>>8, dk = (c>>3)&31, sg = c&7; dst offset = c*16.
    auto fill = [&](int buf, int it) {
        #pragma unroll
        for (int e = 0; e < 4; e++) {
            const int c  = t + e * 128;           // 0..511
            const int h  = c >> 8;
            const int dk = (c >> 3) & 31;
            const int sg = c & 7;
            const int d  = h * 128 + it * PDK + dk;
            const uint32_t dst = (uint32_t)(buf * PA_BUF + c * 16);
            cp_async16(sA + dst, &g_a[d * M_ + ma + sg * 4]);
            cp_async16(sC + dst, &g_c[d * M_ + mc + sg * 4]);
        }
    };

    fill(0, 0); cp_commit();
    fill(1, 1); cp_commit();

    float2 acc[4][2];
    #pragma unroll
    for (int mi = 0; mi < 4; mi++) {
        acc[mi][0] = make_float2(0.f, 0.f);
        acc[mi][1] = make_float2(0.f, 0.f);
    }

    for (int it = 0; it < PITERS; it++) {
        const int cur = it & 1;
        cp_wait1();
        __syncthreads();

        const int dbase = hd * 128 + it * PDK;
        #pragma unroll
        for (int g = 0; g < PDK / 4; g++) {
            const float4 wva = *(const float4*)&Ws2[2 * (dbase + g * 4)];
            const float4 wvb = *(const float4*)&Ws2[2 * (dbase + g * 4) + 4];
            const float2 wp[4] = {
                make_float2(wva.x, wva.y), make_float2(wva.z, wva.w),
                make_float2(wvb.x, wvb.y), make_float2(wvb.z, wvb.w)
            };
            #pragma unroll
            for (int e = 0; e < 4; e++) {
                const int dk = g * 4 + e;
                const float4 av = *(const float4*)&As[cur][hd][dk][ty * 4];
                const float4 cv = *(const float4*)&Cs[cur][hd][dk][tx * 4];
                const float2 c01 = make_float2(cv.x, cv.y);
                const float2 c23 = make_float2(cv.z, cv.w);
                const float am[4] = {av.x, av.y, av.z, av.w};
                #pragma unroll
                for (int mi = 0; mi < 4; mi++) {
                    const float2 ap = make_float2(am[mi], am[mi]);
                    float2 s0 = fadd2(ap, c01);
                    float2 s1 = fadd2(ap, c23);
                    s0.x = fmaxf(s0.x, 0.f); s0.y = fmaxf(s0.y, 0.f);
                    s1.x = fmaxf(s1.x, 0.f); s1.y = fmaxf(s1.y, 0.f);
                    acc[mi][0] = ffma2(s0, wp[e], acc[mi][0]);
                    acc[mi][1] = ffma2(s1, wp[e], acc[mi][1]);
                }
            }
        }

        if (it + 2 < PITERS) {
            __syncthreads();
            fill(cur, it + 2);
        }
        cp_commit();
    }

    // cross-half reduction: upper half stores, lower half combines + writes
    if (t >= 64) {
        const int u = t - 64;
        #pragma unroll
        for (int mi = 0; mi < 4; mi++)
            *(float4*)&red[u][mi * 4] =
                make_float4(acc[mi][0].x, acc[mi][0].y,
                            acc[mi][1].x, acc[mi][1].y);
    }
    __syncthreads();
    if (t < 64) {
        const float bb = b2[0];
        const int j = j0 + tx * 4;
        #pragma unroll
        for (int mi = 0; mi < 4; mi++) {
            const float4 r = *(const float4*)&red[t][mi * 4];
            const int i = i0 + ty * 4 + mi;
            float4 o;
            o.x = acc[mi][0].x + r.x + bb;
            o.y = acc[mi][0].y + r.y + bb;
            o.z = acc[mi][1].x + r.z + bb;
            o.w = acc[mi][1].y + r.w + bb;
            *(float4*)&out[((size_t)b * N_ + i) * N_ + j] = o;
        }
    }
}

// ---------------------------------------------------------------------------
extern "C" void kernel_launch(void* const* d_in, const int* in_sizes, int n_in,
                              void* d_out, int out_size)
{
    const float* emb = (const float*)d_in[0];
    const float* W1  = (const float*)d_in[1];
    const float* b1  = (const float*)d_in[2];
    const float* W2  = (const float*)d_in[3];
    const float* b2  = (const float*)d_in[4];
    float* out = (float*)d_out;

    prep_kernel<<<EMB_BLOCKS + W_BLOCKS, 256>>>(emb, W1);    // 480 blocks

    dim3 ggrid(N_ / 64, M_ / 128);                           // 8 x 16 = 128
    gemm_kernel<<<ggrid, 256>>>(b1);

    dim3 pgrid(N_ / 32, N_ / 32, B_);                        // 16 x 16 x 4
    pair_kernel<<<pgrid, 128>>>(W2, b2, out);
}